// round 17
// baseline (speedup 1.0000x reference)
#include <cuda_runtime.h>
#include <cuda_fp16.h>
#include <cstdint>

#define NFINE   1000000
#define NCOARSE 250000
#define FE      9
#define NF      64
#define BLOCK_M 32               // per warp-pipeline tile
#define THREADS 512              // 16 independent warp pipelines
#define NGRP    16
#define NBUF    3                // slab buffers per warp (produce-ahead 2)
#define BSTRIDE 148              // B n-major row stride (u32 words) == 20 mod 32 ->
                                 // 8-row ldmatrix phases hit disjoint bank quads
#define ASTRIDE 20               // A row stride (u32 words): same conflict-free pattern

// smem layout (u32 units)
#define WS_U32   (NF * BSTRIDE)                // 9472 (W as [n][k] halves, shared)
#define A_U32    (BLOCK_M * ASTRIDE)           // 640 per slab buffer
#define AG_U32   (NBUF * A_U32)                // 1920 per warp
#define A_OFF(g)   (WS_U32 + (g) * AG_U32)
#define IDX_U32  (BLOCK_M * FE)                // 288 per idx buffer
#define IDX_OFF(g) (WS_U32 + NGRP * AG_U32 + (g) * 2 * IDX_U32)
#define SMEM_U32 (WS_U32 + NGRP * AG_U32 + NGRP * 2 * IDX_U32)  // 49408
#define SMEM_BYTES (SMEM_U32 * 4)              // 197632 B -> 1 CTA/SM

// fp16 copy of coarse values (filled by conv_coarse pre-pass each launch)
__device__ __half g_ch[NCOARSE * 32];          // 16 MB

__global__ void __launch_bounds__(256)
conv_coarse(const float4* __restrict__ src)
{
    uint2* dst = (uint2*)g_ch;
    const int n4 = NCOARSE * 8;
    for (int i = blockIdx.x * blockDim.x + threadIdx.x; i < n4;
         i += gridDim.x * blockDim.x) {
        float4 v = src[i];
        __half2 h0 = __floats2half2_rn(v.x, v.y);
        __half2 h1 = __floats2half2_rn(v.z, v.w);
        dst[i] = make_uint2(*(uint32_t*)&h0, *(uint32_t*)&h1);
    }
}

__device__ __forceinline__ void cp_commit() { asm volatile("cp.async.commit_group;"); }
template<int N> __device__ __forceinline__ void cp_wait() {
    // Warp instruction: retires only when every lane's pending groups <= N.
    asm volatile("cp.async.wait_group %0;" :: "n"(N));
}
__device__ __forceinline__ void ldsm_x4(uint32_t* r, uint32_t addr) {
    asm volatile("ldmatrix.sync.aligned.m8n8.x4.shared.b16 {%0,%1,%2,%3}, [%4];"
                 : "=r"(r[0]), "=r"(r[1]), "=r"(r[2]), "=r"(r[3]) : "r"(addr));
}

// Gather one neighbor slab j: 32 rows x 64B, 4 cp.async(16B) per lane (warp-private).
__device__ __forceinline__ void gather_slab(const int* __restrict__ sidx, int j,
                                            uint32_t abuf, int lane)
{
    #pragma unroll
    for (int i = 0; i < 4; ++i) {
        int o   = i * 32 + lane;               // 0..127
        int r   = o >> 2;
        int seg = o & 3;
        int idx = sidx[r * FE + j];
        const char* src = (const char*)g_ch + ((size_t)(unsigned)idx << 6) + (seg << 4);
        uint32_t dst = abuf + (uint32_t)r * (ASTRIDE * 4) + (uint32_t)(seg << 4);
        asm volatile("cp.async.cg.shared.global [%0], [%1], 16;" :: "r"(dst), "l"(src));
    }
}

// Stage 32x9 neighbor indices for one tile (tail: per-element clamp). Warp-private.
__device__ __forceinline__ void stage_idx(const int* __restrict__ nbr, int tile,
                                          uint32_t dst, int lane)
{
    const size_t base = (size_t)tile * (BLOCK_M * FE);
    if (base + BLOCK_M * FE <= (size_t)NFINE * FE) {
        #pragma unroll
        for (int c = lane; c < BLOCK_M * FE / 4; c += 32)
            asm volatile("cp.async.ca.shared.global [%0], [%1], 16;"
                         :: "r"(dst + c * 16), "l"(nbr + base + c * 4));
    } else {
        const size_t gmax = (size_t)NFINE * FE - 1;
        for (int i = lane; i < BLOCK_M * FE; i += 32) {
            size_t g = base + i; if (g > gmax) g = gmax;
            asm volatile("cp.async.ca.shared.global [%0], [%1], 4;"
                         :: "r"(dst + i * 4), "l"(nbr + g));
        }
    }
}

__global__ void __launch_bounds__(THREADS, 1)
finefy_fp16_kernel(const int*   __restrict__ nbr,
                   const float* __restrict__ weight,
                   float*       __restrict__ out,
                   int numTiles)
{
    extern __shared__ uint32_t sm_[];
    const uint32_t sb = (uint32_t)__cvta_generic_to_shared(sm_);

    const int tid  = threadIdx.x;
    const int grp  = tid >> 5;       // warp pipeline 0..15
    const int lane = tid & 31;
    const int qr   = lane >> 2;      // 0..7
    const int qc   = lane & 3;       // 0..3

    // Weight -> fp16 n-major: half index = n*(BSTRIDE*2) + k. One-time scatter.
    for (int i = tid; i < 288 * NF; i += THREADS) {
        int k = i >> 6, n = i & 63;
        ((__half*)sm_)[n * (BSTRIDE * 2) + k] = __float2half_rn(weight[i]);
    }
    __syncthreads();   // only CTA-wide barrier; warps run independently after this

    const uint32_t a_base   = sb + A_OFF(grp) * 4;
    const uint32_t idx_base = sb + IDX_OFF(grp) * 4;

    // Per-lane ldmatrix address offsets (bytes).
    const uint32_t a_lane_off = (((lane & 15) * ASTRIDE) + ((lane >> 4) * 4)) * 4;
    const uint32_t b_lane_off = (uint32_t)(((lane >> 3) << 3) + (lane & 7))
                                * (BSTRIDE * 4);

    const int step = gridDim.x * NGRP;
    int tile = blockIdx.x * NGRP + grp;
    int ibuf = 0;       // idx buffer holding current tile's indices
    int cons = 0;       // slab buffer about to be consumed (cycles mod 3)

    // ---- Prologue: stage idx, then fill 2 of the 3 slab buffers ----
    if (tile < numTiles) {
        stage_idx(nbr, tile, idx_base, lane);
        cp_commit(); cp_wait<0>();
        const int* sidx0 = (const int*)(sm_ + IDX_OFF(grp));
        #pragma unroll
        for (int p = 0; p < 2; ++p) {
            gather_slab(sidx0, p, a_base + p * (A_U32 * 4), lane);
            cp_commit();
        }
    }

    for (; tile < numTiles; tile += step) {
        const int* sidx  = (const int*)(sm_ + IDX_OFF(grp) + ibuf * IDX_U32);
        const int* nsidx = (const int*)(sm_ + IDX_OFF(grp) + (ibuf ^ 1) * IDX_U32);
        const bool has_next = (tile + step) < numTiles;

        float acc[2][8][4];   // [m16-half][n8-tile][frag]
        #pragma unroll
        for (int i = 0; i < 2; ++i)
            #pragma unroll
            for (int t = 0; t < 8; ++t) {
                acc[i][t][0] = 0.f; acc[i][t][1] = 0.f;
                acc[i][t][2] = 0.f; acc[i][t][3] = 0.f;
            }

        #pragma unroll
        for (int j = 0; j < FE; ++j) {
            cp_wait<1>();      // all lanes' slab-j copies landed (warp-collective)

            // ---- Produce slab j+2 into slab j-1's buffer ((cons+2)%3).
            //      Program order already puts this after slab j-1's LDSM reads. ----
            uint32_t freed = a_base + ((cons + 2) % NBUF) * (A_U32 * 4);
            if (j + 2 < FE) {
                gather_slab(sidx, j + 2, freed, lane);
                if (j == 0 && has_next)  // lands by j=2's wait; first used at j=7
                    stage_idx(nbr, tile + step, idx_base + (ibuf ^ 1) * (IDX_U32 * 4), lane);
            } else if (has_next) {
                gather_slab(nsidx, j - 7, freed, lane);   // next tile's slabs 0..1
            }
            cp_commit();       // exactly one group per j (possibly empty)

            // ---- Compute slab j from buffer `cons`: warp tile m32 x n64.
            //      All LDSM hoisted per kk so load latencies overlap, then a
            //      dense 16-MMA issue run. ----
            const uint32_t a_slab = a_base + cons * (A_U32 * 4) + a_lane_off;
            const uint32_t b_slab = sb + b_lane_off + (uint32_t)j * 64;  // j*32 halves

            #pragma unroll
            for (int kk = 0; kk < 2; ++kk) {     // two k16 steps cover 32 dims
                uint32_t b0l[4], b0h[4], b1l[4], b1h[4];
                uint32_t a0[4], a1[4];
                ldsm_x4(b0l, b_slab + kk * 32);                       // t=0..3, k lo
                ldsm_x4(b0h, b_slab + kk * 32 + 16);                  // t=0..3, k hi
                ldsm_x4(b1l, b_slab + 32 * (BSTRIDE * 4) + kk * 32);       // t=4..7
                ldsm_x4(b1h, b_slab + 32 * (BSTRIDE * 4) + kk * 32 + 16);
                ldsm_x4(a0, a_slab + (uint32_t)(kk * 8) * 4);              // m 0..15
                ldsm_x4(a1, a_slab + (uint32_t)(16 * ASTRIDE + kk * 8) * 4); // m16..31

                #pragma unroll
                for (int s2 = 0; s2 < 2; ++s2) { // two m16 halves of m32
                    const uint32_t* a = s2 ? a1 : a0;
                    #pragma unroll
                    for (int t = 0; t < 8; ++t) {
                        uint32_t bb0 = (t < 4) ? b0l[t] : b1l[t - 4];
                        uint32_t bb1 = (t < 4) ? b0h[t] : b1h[t - 4];
                        asm volatile(
                            "mma.sync.aligned.m16n8k16.row.col.f32.f16.f16.f32 "
                            "{%0,%1,%2,%3}, {%4,%5,%6,%7}, {%8,%9}, {%0,%1,%2,%3};"
                            : "+f"(acc[s2][t][0]), "+f"(acc[s2][t][1]),
                              "+f"(acc[s2][t][2]), "+f"(acc[s2][t][3])
                            : "r"(a[0]), "r"(a[1]), "r"(a[2]), "r"(a[3]),
                              "r"(bb0), "r"(bb1));
                    }
                }
            }
            cons = (cons + 1) % NBUF;
        }

        // Epilogue: next tile's slabs 0..1 land underneath these stores.
        const int rowbase = tile * BLOCK_M;
        #pragma unroll
        for (int s2 = 0; s2 < 2; ++s2) {
            #pragma unroll
            for (int h = 0; h < 2; ++h) {
                int r = rowbase + s2 * 16 + h * 8 + qr;
                if (r < NFINE) {
                    float2* po = (float2*)(out + (size_t)r * NF + qc * 2);
                    #pragma unroll
                    for (int t = 0; t < 8; ++t)
                        __stcs(po + t * 4,
                               make_float2(acc[s2][t][2*h], acc[s2][t][2*h + 1]));
                }
            }
        }
        ibuf ^= 1;
    }
}

extern "C" void kernel_launch(void* const* d_in, const int* in_sizes, int n_in,
                              void* d_out, int out_size)
{
    const float* coarse = (const float*)d_in[0];   // [250000, 32] f32
    const int*   nbr    = (const int*)  d_in[1];   // [1000000, 9] i32
    const float* weight = (const float*)d_in[2];   // [288, 64] f32
    float*       out    = (float*)d_out;           // [1000000, 64] f32

    cudaFuncSetAttribute(finefy_fp16_kernel,
                         cudaFuncAttributeMaxDynamicSharedMemorySize, SMEM_BYTES);

    int nsm = 148;
    cudaDeviceGetAttribute(&nsm, cudaDevAttrMultiProcessorCount, 0);

    // Pre-pass: convert coarse lattice to fp16 (deterministic, graph-capturable).
    conv_coarse<<<nsm * 4, 256>>>((const float4*)coarse);

    const int numTiles = (NFINE + BLOCK_M - 1) / BLOCK_M;   // 31250
    finefy_fp16_kernel<<<nsm, THREADS, SMEM_BYTES>>>(nbr, weight, out, numTiles);
}